// round 13
// baseline (speedup 1.0000x reference)
#include <cuda_runtime.h>
#include <cuda_fp16.h>
#include <math.h>
#include <stdint.h>

// ---------------- problem constants ----------------
#define BB     8
#define CC     96
#define NN     3136
#define COUT   192
#define TK     64
#define NTILE  49
#define QTM    64
#define KSPLIT 3

// ---------------- scratch ----------------
__device__ alignas(16) __half g_xhi[BB * CC * NN];
__device__ alignas(16) __half g_xlo[BB * CC * NN];
__device__ alignas(16) __half g_xjhi[BB * CC * NN];
__device__ alignas(16) __half g_xjlo[BB * CC * NN];
__device__ alignas(16) __half g_whi[COUT * 2 * CC];
__device__ alignas(16) __half g_wlo[COUT * 2 * CC];
__device__ alignas(16) unsigned char g_q8a[(size_t)BB * NN * 128];  // token-major int8 lvl1
__device__ alignas(16) unsigned char g_q8b[(size_t)BB * NN * 128];  // lvl2 (residual/254)
__device__ alignas(16) float g_dlt[BB * NN];   // per-token scale
__device__ float g_norm[BB * NN];
__device__ int   g_maxn[BB];
__device__ alignas(16) float g_att[BB * CC * NN];
__device__ alignas(16) float g_l[BB * NN];
__device__ float g_y[BB * COUT * NN];
__device__ float g_sum[COUT];
__device__ float g_sumsq[COUT];

// ---------------- attn smem layout ----------------
#define OFF_Q8A 0
#define OFF_Q8B 8192
#define OFF_KST 16384
#define KST_STRIDE 29184          // K8A 8192 + K8B 8192 + VH 12288 + SC 256 (pad->29184)
#define KS_K8A 0
#define KS_K8B 8192
#define KS_VH  16384
#define KS_SC  28672
#define ATT_SMEM (OFF_KST + 2 * KST_STRIDE)   // 74752

// ---------------- conv smem layout (z-split: 96 outputs/block) ----------------
#define CV_CAT_HI 0
#define CV_CAT_LO 24576
#define CV_W      49152
#define CV_WHALF  3328
#define CV_WSTAGE 6656
#define CV_SMEM   (CV_W + 2 * CV_WSTAGE)

#define PREP_SMEM (2 * 256 * 33 * 4)   // 67584

// ---------------- PTX helpers ----------------
__device__ __forceinline__ uint32_t smem_u32(const void* p) {
    uint32_t a;
    asm("{ .reg .u64 t; cvta.to.shared.u64 t, %1; cvt.u32.u64 %0, t; }" : "=r"(a) : "l"(p));
    return a;
}
__device__ __forceinline__ uint32_t swk(uint32_t o) { return o ^ ((o >> 3) & 0x70); }

__device__ __forceinline__ void ldsm4(uint32_t* r, uint32_t a) {
    asm volatile("ldmatrix.sync.aligned.m8n8.x4.shared.b16 {%0,%1,%2,%3}, [%4];"
                 : "=r"(r[0]), "=r"(r[1]), "=r"(r[2]), "=r"(r[3]) : "r"(a));
}
__device__ __forceinline__ void ldsm4t(uint32_t* r, uint32_t a) {
    asm volatile("ldmatrix.sync.aligned.m8n8.x4.trans.shared.b16 {%0,%1,%2,%3}, [%4];"
                 : "=r"(r[0]), "=r"(r[1]), "=r"(r[2]), "=r"(r[3]) : "r"(a));
}
__device__ __forceinline__ void mma16816(float* d, const uint32_t* a,
                                         uint32_t b0, uint32_t b1) {
    asm volatile(
        "mma.sync.aligned.m16n8k16.row.col.f32.f16.f16.f32 "
        "{%0,%1,%2,%3}, {%4,%5,%6,%7}, {%8,%9}, {%0,%1,%2,%3};"
        : "+f"(d[0]), "+f"(d[1]), "+f"(d[2]), "+f"(d[3])
        : "r"(a[0]), "r"(a[1]), "r"(a[2]), "r"(a[3]), "r"(b0), "r"(b1));
}
__device__ __forceinline__ void imma16832(int* d, const uint32_t* a,
                                          uint32_t b0, uint32_t b1) {
    asm volatile(
        "mma.sync.aligned.m16n8k32.row.col.s32.s8.s8.s32 "
        "{%0,%1,%2,%3}, {%4,%5,%6,%7}, {%8,%9}, {%0,%1,%2,%3};"
        : "+r"(d[0]), "+r"(d[1]), "+r"(d[2]), "+r"(d[3])
        : "r"(a[0]), "r"(a[1]), "r"(a[2]), "r"(a[3]), "r"(b0), "r"(b1));
}
__device__ __forceinline__ void cpasync16(uint32_t dst, const void* src) {
    asm volatile("cp.async.cg.shared.global [%0], [%1], 16;" :: "r"(dst), "l"(src));
}
#define CP_COMMIT() asm volatile("cp.async.commit_group;" ::: "memory")
#define CP_WAIT1()  asm volatile("cp.async.wait_group 1;" ::: "memory")
#define CP_WAIT0()  asm volatile("cp.async.wait_group 0;" ::: "memory")

__device__ __forceinline__ uint32_t packh2(float a, float b) {
    __half2 h = __floats2half2_rn(a, b);
    return *reinterpret_cast<uint32_t*>(&h);
}
__device__ __forceinline__ void split2h(float a, float b, uint32_t& hi, uint32_t& lo) {
    __half2 h = __floats2half2_rn(a, b);
    float2 hf = __half22float2(h);
    __half2 l = __floats2half2_rn(a - hf.x, b - hf.y);
    hi = *reinterpret_cast<uint32_t*>(&h);
    lo = *reinterpret_cast<uint32_t*>(&l);
}

// ---------------------------------------------------------------------------
// Kernel 0a: per-token stats + fp16 hi/lo split + dual-int8 quantization
// (token-major, smem-staged for coalesced writes) + zero O/l accumulators.
// ---------------------------------------------------------------------------
__global__ __launch_bounds__(256)
void prep_kernel(const float* __restrict__ x)
{
    extern __shared__ uint32_t sq[];         // [2][256][33]
    uint32_t* s1 = sq;
    uint32_t* s2 = sq + 256 * 33;
    const int tid = threadIdx.x;
    const int b = blockIdx.y;
    const int n = blockIdx.x * 256 + tid;
    const bool ok = (n < NN);
    const float* xb = x + (size_t)b * CC * NN;
    __half* hb = g_xhi + (size_t)b * CC * NN;
    __half* lb = g_xlo + (size_t)b * CC * NN;
    float* ob = g_att + (size_t)b * CC * NN;

    // pass 1: maxabs + norm
    float aa = 0.f, s = 0.f;
    if (ok) {
        for (int c = 0; c < CC; c++) {
            float v = xb[c * NN + n];
            aa = fmaxf(aa, fabsf(v));
            s = fmaf(v, v, s);
        }
    }
    const float dlt = fmaxf(aa, 1e-12f) * (1.f / 127.f);
    const float invd = 127.f / fmaxf(aa, 1e-12f);
    const float invd2 = invd * 254.f;
    if (ok) {
        g_dlt[b * NN + n] = dlt;
        float norm = sqrtf(s);
        g_norm[b * NN + n] = norm;
        g_l[b * NN + n] = 0.f;
        atomicMax(&g_maxn[b], __float_as_int(norm));
    }

    // pass 2: fp16 split + int8 quantize into smem staging
    for (int c4 = 0; c4 < 32; c4++) {
        uint32_t w1 = 0, w2 = 0;
#pragma unroll
        for (int j = 0; j < 4; j++) {
            int c = c4 * 4 + j;
            float v = (ok && c < CC) ? xb[c * NN + n] : 0.f;
            if (ok && c < CC) {
                __half h = __float2half_rn(v);
                hb[c * NN + n] = h;
                lb[c * NN + n] = __float2half_rn(v - __half2float(h));
                ob[c * NN + n] = 0.f;
            }
            float q1 = rintf(v * invd);
            float r  = fmaf(-q1, dlt, v);
            float q2 = rintf(r * invd2);
            w1 |= ((uint32_t)(uint8_t)(int)q1) << (8 * j);
            w2 |= ((uint32_t)(uint8_t)(int)q2) << (8 * j);
        }
        s1[tid * 33 + c4] = w1;
        s2[tid * 33 + c4] = w2;
    }
    __syncthreads();

    // cooperative coalesced write (32 u32 per token)
    const int base = blockIdx.x * 256;
    uint32_t* qa = (uint32_t*)(g_q8a + ((size_t)b * NN + base) * 128);
    uint32_t* qb = (uint32_t*)(g_q8b + ((size_t)b * NN + base) * 128);
    const int lim = (NN - base < 256 ? NN - base : 256) * 32;
    for (int idx = tid; idx < lim; idx += 256) {
        int tk = idx >> 5, w = idx & 31;
        qa[idx] = s1[tk * 33 + w];
        qb[idx] = s2[tk * 33 + w];
    }
}

// ---------------------------------------------------------------------------
// Kernel 0b: split + transpose W, zero BN stat accumulators
// ---------------------------------------------------------------------------
__global__ __launch_bounds__(256)
void wprep_kernel(const float* __restrict__ w)
{
    const int i = blockIdx.x * 256 + threadIdx.x;
    if (i < COUT) { g_sum[i] = 0.f; g_sumsq[i] = 0.f; }
    if (i >= COUT * 2 * CC) return;
    const int o = i / (2 * CC), c = i % (2 * CC);
    float v = w[i];
    __half h = __float2half_rn(v);
    g_whi[c * COUT + o] = h;
    g_wlo[c * COUT + o] = __float2half_rn(v - __half2float(h));
}

// ---------------------------------------------------------------------------
// Kernel 1: flash attention. S via dual-int8 IMMA (4 products: exact int32,
// reconstructed d_i*d_j*(c11 + c12/254 + c22/254^2)); softmax online per-block;
// PV single fp16 product; split-K fp32 atomics in static-bound frame.
// Grid (49, 8, 3) x 128 threads (4 warps; warp w -> query rows 16w..16w+15).
// ---------------------------------------------------------------------------
__global__ __launch_bounds__(128)
void attn_kernel()
{
    extern __shared__ char smc[];
    const uint32_t sb = smem_u32(smc);
    const int tid = threadIdx.x;
    const int lane = tid & 31, warp = tid >> 5;
    const int b  = blockIdx.y;
    const int n0 = blockIdx.x * QTM;
    const int tb = blockIdx.z * 16;
    const int te = (blockIdx.z == KSPLIT - 1) ? NTILE : tb + 16;
    const __half* xh = g_xhi + (size_t)b * CC * NN;
    const unsigned char* qga = g_q8a + ((size_t)b * NN) * 128;
    const unsigned char* qgb = g_q8b + ((size_t)b * NN) * 128;
    const float* dltb = g_dlt + b * NN;

    // Q int8 tiles (64 rows x 128B x 2 levels)
    for (int i = tid; i < 64 * 8; i += 128) {
        int row = i >> 3, ck = i & 7;
        uint32_t d = swk((uint32_t)(row * 128 + ck * 16));
        cpasync16(sb + OFF_Q8A + d, qga + (size_t)(n0 + row) * 128 + ck * 16);
        cpasync16(sb + OFF_Q8B + d, qgb + (size_t)(n0 + row) * 128 + ck * 16);
    }
    // first K stage: K int8 x2 + V fp16 hi + scales
    {
        const int k0 = tb * TK;
        const uint32_t ks = sb + OFF_KST;
        for (int i = tid; i < 64 * 8; i += 128) {
            int row = i >> 3, ck = i & 7;
            uint32_t d = swk((uint32_t)(row * 128 + ck * 16));
            cpasync16(ks + KS_K8A + d, qga + (size_t)(k0 + row) * 128 + ck * 16);
            cpasync16(ks + KS_K8B + d, qgb + (size_t)(k0 + row) * 128 + ck * 16);
        }
        for (int i = tid; i < CC * 8; i += 128) {
            int c = i >> 3, ck = i & 7;
            uint32_t d = swk((uint32_t)(c * 128 + ck * 16));
            cpasync16(ks + KS_VH + d, xh + c * NN + k0 + ck * 8);
        }
        if (tid < 16) cpasync16(ks + KS_SC + tid * 16, dltb + k0 + tid * 4);
    }
    CP_COMMIT();

    const float mnorm = __int_as_float(g_maxn[b]);
    const int q0g = warp * 16 + (lane >> 2);
    const int q1g = q0g + 8;
    const float mi0 = g_norm[b * NN + n0 + q0g] * mnorm;
    const float mi1 = g_norm[b * NN + n0 + q1g] * mnorm;
    const float di0 = dltb[n0 + q0g];
    const float di1 = dltb[n0 + q1g];
    const float INV254  = 1.f / 254.f;
    const float INV254S = 1.f / (254.f * 254.f);

    float oacc[12][4];
#pragma unroll
    for (int f = 0; f < 12; f++)
#pragma unroll
        for (int e = 0; e < 4; e++) oacc[f][e] = 0.f;
    float l0 = 0.f, l1 = 0.f;
    float m0 = -1e30f, m1 = -1e30f;

    uint32_t qa1[3][4], qa2[3][4];
    const int g  = lane >> 3;
    const int lr = lane & 7;

#pragma unroll 1
    for (int t = tb; t < te; t++) {
        __syncthreads();
        if (t + 1 < te) {
            const int k0 = (t + 1) * TK;
            const uint32_t ks = sb + OFF_KST + (uint32_t)((t + 1 - tb) & 1) * KST_STRIDE;
            for (int i = tid; i < 64 * 8; i += 128) {
                int row = i >> 3, ck = i & 7;
                uint32_t d = swk((uint32_t)(row * 128 + ck * 16));
                cpasync16(ks + KS_K8A + d, qga + (size_t)(k0 + row) * 128 + ck * 16);
                cpasync16(ks + KS_K8B + d, qgb + (size_t)(k0 + row) * 128 + ck * 16);
            }
            for (int i = tid; i < CC * 8; i += 128) {
                int c = i >> 3, ck = i & 7;
                uint32_t d = swk((uint32_t)(c * 128 + ck * 16));
                cpasync16(ks + KS_VH + d, xh + c * NN + k0 + ck * 8);
            }
            if (tid < 16) cpasync16(ks + KS_SC + tid * 16, dltb + k0 + tid * 4);
            CP_COMMIT();
            CP_WAIT1();
        } else {
            CP_WAIT0();
        }
        __syncthreads();

        if (t == tb) {  // Q A-fragments (int8, stable afterwards)
#pragma unroll
            for (int ks2 = 0; ks2 < 3; ks2++) {
                uint32_t d = swk((uint32_t)((warp * 16 + (lane & 15)) * 128 +
                                            ks2 * 32 + (lane >> 4) * 16));
                ldsm4(qa1[ks2], sb + OFF_Q8A + d);
                ldsm4(qa2[ks2], sb + OFF_Q8B + d);
            }
        }

        const uint32_t kst = sb + OFF_KST + (uint32_t)((t - tb) & 1) * KST_STRIDE;

        // ---- S = Q K^T (dual-int8, 4 products) ----
        float sacc[8][4];
#pragma unroll
        for (int jg = 0; jg < 4; jg++) {
            int c11[8], c12[8], c22[8];
#pragma unroll
            for (int e = 0; e < 8; e++) { c11[e] = 0; c12[e] = 0; c22[e] = 0; }
#pragma unroll
            for (int ks2 = 0; ks2 < 3; ks2++) {
                uint32_t off = swk((uint32_t)((16 * jg + (lane & 15)) * 128 +
                                              ks2 * 32 + (lane >> 4) * 16));
                uint32_t kra[4], krb[4];
                ldsm4(kra, kst + KS_K8A + off);
                ldsm4(krb, kst + KS_K8B + off);
                imma16832(c11,     qa1[ks2], kra[0], kra[2]);
                imma16832(c11 + 4, qa1[ks2], kra[1], kra[3]);
                imma16832(c12,     qa1[ks2], krb[0], krb[2]);
                imma16832(c12 + 4, qa1[ks2], krb[1], krb[3]);
                imma16832(c12,     qa2[ks2], kra[0], kra[2]);
                imma16832(c12 + 4, qa2[ks2], kra[1], kra[3]);
                imma16832(c22,     qa2[ks2], krb[0], krb[2]);
                imma16832(c22 + 4, qa2[ks2], krb[1], krb[3]);
            }
            float2 dj0 = *(const float2*)(smc + (kst - sb) + KS_SC +
                                          (16 * jg + 2 * (lane & 3)) * 4);
            float2 dj1 = *(const float2*)(smc + (kst - sb) + KS_SC +
                                          (16 * jg + 8 + 2 * (lane & 3)) * 4);
#pragma unroll
            for (int h = 0; h < 2; h++) {
                const int* pc11 = c11 + 4 * h;
                const int* pc12 = c12 + 4 * h;
                const int* pc22 = c22 + 4 * h;
                float2 dj = h ? dj1 : dj0;
#pragma unroll
                for (int e = 0; e < 4; e++) {
                    float v = __int2float_rn(pc11[e]) +
                              __int2float_rn(pc12[e]) * INV254 +
                              __int2float_rn(pc22[e]) * INV254S;
                    float di = (e < 2) ? di0 : di1;
                    float djv = (e & 1) ? dj.y : dj.x;
                    sacc[2 * jg + h][e] = v * di * djv;
                }
            }
        }

        // ---- online row max; rescale only when the max rises ----
        float mx0 = -1e30f, mx1 = -1e30f;
#pragma unroll
        for (int f = 0; f < 8; f++) {
            mx0 = fmaxf(mx0, fmaxf(sacc[f][0], sacc[f][1]));
            mx1 = fmaxf(mx1, fmaxf(sacc[f][2], sacc[f][3]));
        }
        mx0 = fmaxf(mx0, __shfl_xor_sync(0xffffffffu, mx0, 1));
        mx0 = fmaxf(mx0, __shfl_xor_sync(0xffffffffu, mx0, 2));
        mx1 = fmaxf(mx1, __shfl_xor_sync(0xffffffffu, mx1, 1));
        mx1 = fmaxf(mx1, __shfl_xor_sync(0xffffffffu, mx1, 2));
        if (mx0 > m0) {
            float sc0 = __expf(m0 - mx0);
            m0 = mx0; l0 *= sc0;
#pragma unroll
            for (int f = 0; f < 12; f++) { oacc[f][0] *= sc0; oacc[f][1] *= sc0; }
        }
        if (mx1 > m1) {
            float sc1 = __expf(m1 - mx1);
            m1 = mx1; l1 *= sc1;
#pragma unroll
            for (int f = 0; f < 12; f++) { oacc[f][2] *= sc1; oacc[f][3] *= sc1; }
        }

        // ---- softmax -> fp16 P A-frags ----
        uint32_t pah[4][4];
#pragma unroll
        for (int jj = 0; jj < 4; jj++) {
            float p0 = __expf(sacc[2 * jj][0] - m0);
            float p1 = __expf(sacc[2 * jj][1] - m0);
            float p2 = __expf(sacc[2 * jj][2] - m1);
            float p3 = __expf(sacc[2 * jj][3] - m1);
            float p4 = __expf(sacc[2 * jj + 1][0] - m0);
            float p5 = __expf(sacc[2 * jj + 1][1] - m0);
            float p6 = __expf(sacc[2 * jj + 1][2] - m1);
            float p7 = __expf(sacc[2 * jj + 1][3] - m1);
            l0 += (p0 + p1) + (p4 + p5);
            l1 += (p2 + p3) + (p6 + p7);
            pah[jj][0] = packh2(p0, p1);
            pah[jj][1] = packh2(p2, p3);
            pah[jj][2] = packh2(p4, p5);
            pah[jj][3] = packh2(p6, p7);
        }

        // ---- O += P V (fp16, single product) ----
#pragma unroll
        for (int jj = 0; jj < 4; jj++) {
#pragma unroll
            for (int cp = 0; cp < 6; cp++) {
                int ch  = 8 * (2 * cp + (g >> 1)) + lr;
                int key = 16 * jj + (g & 1) * 8;
                uint32_t d = swk((uint32_t)(ch * 128 + key * 2));
                uint32_t bh[4];
                ldsm4(bh, kst + KS_VH + d);
                mma16816(oacc[2 * cp],     pah[jj], bh[0], bh[1]);
                mma16816(oacc[2 * cp + 1], pah[jj], bh[2], bh[3]);
            }
        }
    }

    // ---- epilogue: rescale to static-bound frame (fp32), atomics ----
    const float f0 = __expf(m0 - mi0);
    const float f1 = __expf(m1 - mi1);

    l0 += __shfl_xor_sync(0xffffffffu, l0, 1);
    l0 += __shfl_xor_sync(0xffffffffu, l0, 2);
    l1 += __shfl_xor_sync(0xffffffffu, l1, 1);
    l1 += __shfl_xor_sync(0xffffffffu, l1, 2);

    float* ob = g_att + (size_t)b * CC * NN + n0;
#pragma unroll
    for (int nf = 0; nf < 12; nf++) {
        int c = 8 * nf + 2 * (lane & 3);
        atomicAdd(&ob[c * NN + q0g],       oacc[nf][0] * f0);
        atomicAdd(&ob[(c + 1) * NN + q0g], oacc[nf][1] * f0);
        atomicAdd(&ob[c * NN + q1g],       oacc[nf][2] * f1);
        atomicAdd(&ob[(c + 1) * NN + q1g], oacc[nf][3] * f1);
    }
    if ((lane & 3) == 0) {
        atomicAdd(&g_l[b * NN + n0 + q0g], l0 * f0);
        atomicAdd(&g_l[b * NN + n0 + q1g], l1 * f1);
    }
}

// ---------------------------------------------------------------------------
// Kernel 2: finalize attention: xj = relu(x - O/l) -> fp16 hi/lo
// ---------------------------------------------------------------------------
__global__ __launch_bounds__(256)
void attn_fin_kernel(const float* __restrict__ x)
{
    const int i4 = blockIdx.x * 256 + threadIdx.x;
    const int per = CC * NN / 4;
    if (i4 >= BB * per) return;
    const int b = i4 / per, r = i4 - b * per;
    const int n4 = r % (NN / 4);
    float4 o  = ((const float4*)g_att)[i4];
    float4 lv = ((const float4*)g_l)[b * (NN / 4) + n4];
    float4 xv = ((const float4*)x)[i4];
    float j0 = fmaxf(xv.x - o.x / lv.x, 0.f);
    float j1 = fmaxf(xv.y - o.y / lv.y, 0.f);
    float j2 = fmaxf(xv.z - o.z / lv.z, 0.f);
    float j3 = fmaxf(xv.w - o.w / lv.w, 0.f);
    uint2 hi, lo;
    split2h(j0, j1, hi.x, lo.x);
    split2h(j2, j3, hi.y, lo.y);
    ((uint2*)g_xjhi)[i4] = hi;
    ((uint2*)g_xjlo)[i4] = lo;
}

// ---------------------------------------------------------------------------
// Kernel 3: 1x1 conv via fp16-split MMA (3 products) + bias + fused BN stats
// Grid (49, 8, 2) x 128 threads; 96 out channels x 64 tokens per block.
// ---------------------------------------------------------------------------
__global__ __launch_bounds__(128)
void conv_kernel(const float* __restrict__ bias)
{
    extern __shared__ char smc[];
    const uint32_t sb = smem_u32(smc);
    const int tid = threadIdx.x;
    const int lane = tid & 31, warp = tid >> 5;
    const int wy = warp >> 1, wx = warp & 1;
    const int b = blockIdx.y, n0 = blockIdx.x * 64;
    const int zo = blockIdx.z * 96;
    const __half* xh = g_xhi  + (size_t)b * CC * NN;
    const __half* xl = g_xlo  + (size_t)b * CC * NN;
    const __half* jh = g_xjhi + (size_t)b * CC * NN;
    const __half* jl = g_xjlo + (size_t)b * CC * NN;

    for (int i = tid; i < 192 * 8; i += 128) {
        int c = i >> 3, ck = i & 7;
        uint32_t d = swk((uint32_t)(c * 128 + ck * 16));
        const __half* sh = (c < CC) ? (xh + c * NN) : (jh + (c - CC) * NN);
        const __half* sl = (c < CC) ? (xl + c * NN) : (jl + (c - CC) * NN);
        cpasync16(sb + CV_CAT_HI + d, sh + n0 + ck * 8);
        cpasync16(sb + CV_CAT_LO + d, sl + n0 + ck * 8);
    }
    for (int i = tid; i < 16 * 12; i += 128) {
        int rr = i / 12, cc = i % 12;
        cpasync16(sb + CV_W + rr * 208 + cc * 16,            g_whi + rr * COUT + zo + cc * 8);
        cpasync16(sb + CV_W + CV_WHALF + rr * 208 + cc * 16, g_wlo + rr * COUT + zo + cc * 8);
    }
    CP_COMMIT();

    float cacc[3][4][4];
#pragma unroll
    for (int m = 0; m < 3; m++)
#pragma unroll
        for (int n = 0; n < 4; n++)
#pragma unroll
            for (int e = 0; e < 4; e++) cacc[m][n][e] = 0.f;

    const int g = lane >> 3, lr = lane & 7;

#pragma unroll 1
    for (int k = 0; k < 12; k++) {
        if (k + 1 < 12) {
            const uint32_t wb = sb + CV_W + (uint32_t)((k + 1) & 1) * CV_WSTAGE;
            const int k0n = (k + 1) * 16;
            for (int i = tid; i < 16 * 12; i += 128) {
                int rr = i / 12, cc = i % 12;
                cpasync16(wb + rr * 208 + cc * 16,            g_whi + (k0n + rr) * COUT + zo + cc * 8);
                cpasync16(wb + CV_WHALF + rr * 208 + cc * 16, g_wlo + (k0n + rr) * COUT + zo + cc * 8);
            }
            CP_COMMIT();
            CP_WAIT1();
        } else {
            CP_WAIT0();
        }
        __syncthreads();

        const uint32_t wb = sb + CV_W + (uint32_t)(k & 1) * CV_WSTAGE;
        uint32_t ah[3][4], al[3][4];
#pragma unroll
        for (int mf = 0; mf < 3; mf++) {
            int out = 48 * wy + 16 * mf + ((g & 1) ? 8 : 0);
            int chh = ((g >= 2) ? 8 : 0) + lr;
            uint32_t d = (uint32_t)(chh * 208 + out * 2);
            ldsm4t(ah[mf], wb + d);
            ldsm4t(al[mf], wb + CV_WHALF + d);
        }
#pragma unroll
        for (int jp = 0; jp < 2; jp++) {
            int ch  = k * 16 + (g & 1) * 8 + lr;
            int key = 32 * wx + 16 * jp + (g >> 1) * 8;
            uint32_t d = swk((uint32_t)(ch * 128 + key * 2));
            uint32_t bh[4], bl[4];
            ldsm4t(bh, sb + CV_CAT_HI + d);
            ldsm4t(bl, sb + CV_CAT_LO + d);
#pragma unroll
            for (int mf = 0; mf < 3; mf++) {
                mma16816(cacc[mf][2 * jp],     ah[mf], bh[0], bh[1]);
                mma16816(cacc[mf][2 * jp],     ah[mf], bl[0], bl[1]);
                mma16816(cacc[mf][2 * jp],     al[mf], bh[0], bh[1]);
                mma16816(cacc[mf][2 * jp + 1], ah[mf], bh[2], bh[3]);
                mma16816(cacc[mf][2 * jp + 1], ah[mf], bl[2], bl[3]);
                mma16816(cacc[mf][2 * jp + 1], al[mf], bh[2], bh[3]);
            }
        }
        __syncthreads();
    }

    float* ys = (float*)smc;
#pragma unroll
    for (int mf = 0; mf < 3; mf++) {
        int r0 = 48 * wy + 16 * mf + (lane >> 2);
        float b0 = bias[zo + r0], b1 = bias[zo + r0 + 8];
#pragma unroll
        for (int nf = 0; nf < 4; nf++) {
            int tok = 32 * wx + 8 * nf + 2 * (lane & 3);
            ys[r0 * 65 + tok]           = cacc[mf][nf][0] + b0;
            ys[r0 * 65 + tok + 1]       = cacc[mf][nf][1] + b0;
            ys[(r0 + 8) * 65 + tok]     = cacc[mf][nf][2] + b1;
            ys[(r0 + 8) * 65 + tok + 1] = cacc[mf][nf][3] + b1;
        }
    }
    __syncthreads();

    if (tid < 96) {
        float s = 0.f, ss = 0.f;
#pragma unroll 4
        for (int i = 0; i < 64; i++) {
            float v = ys[tid * 65 + i];
            s += v; ss = fmaf(v, v, ss);
        }
        atomicAdd(&g_sum[zo + tid], s);
        atomicAdd(&g_sumsq[zo + tid], ss);
    }

    float* yb = g_y + (size_t)b * COUT * NN + (size_t)zo * NN + n0;
    for (int i = tid; i < 96 * 64; i += 128) {
        int rr = i >> 6, cc = i & 63;
        yb[rr * NN + cc] = ys[rr * 65 + cc];
    }
}

// ---------------------------------------------------------------------------
// Kernel 4: BN apply (scale/shift inline from stats) + exact GELU
// ---------------------------------------------------------------------------
__global__ __launch_bounds__(256)
void bn_gelu_kernel(float* __restrict__ out,
                    const float* __restrict__ gamma,
                    const float* __restrict__ beta)
{
    const int i4 = blockIdx.x * blockDim.x + threadIdx.x;
    const int total4 = BB * COUT * NN / 4;
    if (i4 >= total4) return;
    const int ch = (i4 / (NN / 4)) % COUT;
    const float cnt = (float)(BB * NN);
    const float mean = g_sum[ch] / cnt;
    const float var  = g_sumsq[ch] / cnt - mean * mean;
    const float a    = gamma[ch] * rsqrtf(var + 1e-5f);
    const float sh   = beta[ch] - mean * a;
    float4 v = ((const float4*)g_y)[i4];
    v.x = v.x * a + sh;  v.x = v.x * normcdff(v.x);
    v.y = v.y * a + sh;  v.y = v.y * normcdff(v.y);
    v.z = v.z * a + sh;  v.z = v.z * normcdff(v.z);
    v.w = v.w * a + sh;  v.w = v.w * normcdff(v.w);
    ((float4*)out)[i4] = v;
}

// ---------------------------------------------------------------------------
extern "C" void kernel_launch(void* const* d_in, const int* in_sizes, int n_in,
                              void* d_out, int out_size)
{
    const float* x     = (const float*)d_in[0];
    const float* w     = (const float*)d_in[1];
    const float* cbias = (const float*)d_in[2];
    const float* gamma = (const float*)d_in[3];
    const float* beta  = (const float*)d_in[4];
    float* out = (float*)d_out;

    cudaFuncSetAttribute(prep_kernel, cudaFuncAttributeMaxDynamicSharedMemorySize, PREP_SMEM);
    cudaFuncSetAttribute(attn_kernel, cudaFuncAttributeMaxDynamicSharedMemorySize, ATT_SMEM);
    cudaFuncSetAttribute(conv_kernel, cudaFuncAttributeMaxDynamicSharedMemorySize, CV_SMEM);

    prep_kernel<<<dim3((NN + 255) / 256, BB), 256, PREP_SMEM>>>(x);
    wprep_kernel<<<(COUT * 2 * CC + 255) / 256, 256>>>(w);
    attn_kernel<<<dim3(NTILE, BB, KSPLIT), 128, ATT_SMEM>>>();
    attn_fin_kernel<<<(BB * CC * NN / 4 + 255) / 256, 256>>>(x);
    conv_kernel<<<dim3(NTILE, BB, 2), 128, CV_SMEM>>>(cbias);
    bn_gelu_kernel<<<(BB * COUT * NN / 4 + 255) / 256, 256>>>(out, gamma, beta);
}

// round 15
// speedup vs baseline: 2.6720x; 2.6720x over previous
#include <cuda_runtime.h>
#include <cuda_fp16.h>
#include <math.h>
#include <stdint.h>

// ---------------- problem constants ----------------
#define BB     8
#define CC     96
#define NN     3136
#define COUT   192
#define TK     64
#define NTILE  49          // NN / TK
#define QTM    64          // query rows per attn block
#define KSPLIT 3

// ---------------- scratch ----------------
__device__ alignas(16) __half g_xhi[BB * CC * NN];
__device__ alignas(16) __half g_xlo[BB * CC * NN];
__device__ alignas(16) __half g_xjhi[BB * CC * NN];
__device__ alignas(16) __half g_xjlo[BB * CC * NN];
__device__ alignas(16) __half g_whi[COUT * 2 * CC];   // transposed [ch][out]
__device__ alignas(16) __half g_wlo[COUT * 2 * CC];
__device__ float g_norm[BB * NN];
__device__ int   g_maxn[BB];
__device__ alignas(16) float g_att[BB * CC * NN];   // O accumulator (atomic)
__device__ alignas(16) float g_l[BB * NN];          // l accumulator (atomic)
__device__ float g_y[BB * COUT * NN];
__device__ float g_sum[COUT];
__device__ float g_sumsq[COUT];

// ---------------- attn smem layout ----------------
#define OFF_QHI 0
#define OFF_QLO 12288
#define OFF_K   24576
#define KSTAGE  24576                   // hi 12288 + lo 12288
#define ATT_SMEM (OFF_K + 2 * KSTAGE)   // 73728

// ---------------- conv smem layout (z-split: 96 outputs/block) ----------------
#define CV_CAT_HI 0
#define CV_CAT_LO 24576
#define CV_W      49152                 // + stage*6656 ; hi +0, lo +3328
#define CV_WHALF  3328                  // 16 rows x 208B
#define CV_WSTAGE 6656
#define CV_SMEM   (CV_W + 2 * CV_WSTAGE)  // 62464 (ysm 24960 reuses front)

// ---------------- PTX helpers ----------------
__device__ __forceinline__ uint32_t smem_u32(const void* p) {
    uint32_t a;
    asm("{ .reg .u64 t; cvta.to.shared.u64 t, %1; cvt.u32.u64 %0, t; }" : "=r"(a) : "l"(p));
    return a;
}
__device__ __forceinline__ uint32_t swk(uint32_t o) { return o ^ ((o >> 3) & 0x70); }

__device__ __forceinline__ void ldsm4(uint32_t* r, uint32_t a) {
    asm volatile("ldmatrix.sync.aligned.m8n8.x4.shared.b16 {%0,%1,%2,%3}, [%4];"
                 : "=r"(r[0]), "=r"(r[1]), "=r"(r[2]), "=r"(r[3]) : "r"(a));
}
__device__ __forceinline__ void ldsm4t(uint32_t* r, uint32_t a) {
    asm volatile("ldmatrix.sync.aligned.m8n8.x4.trans.shared.b16 {%0,%1,%2,%3}, [%4];"
                 : "=r"(r[0]), "=r"(r[1]), "=r"(r[2]), "=r"(r[3]) : "r"(a));
}
__device__ __forceinline__ void mma16816(float* d, const uint32_t* a,
                                         uint32_t b0, uint32_t b1) {
    asm volatile(
        "mma.sync.aligned.m16n8k16.row.col.f32.f16.f16.f32 "
        "{%0,%1,%2,%3}, {%4,%5,%6,%7}, {%8,%9}, {%0,%1,%2,%3};"
        : "+f"(d[0]), "+f"(d[1]), "+f"(d[2]), "+f"(d[3])
        : "r"(a[0]), "r"(a[1]), "r"(a[2]), "r"(a[3]), "r"(b0), "r"(b1));
}
__device__ __forceinline__ void cpasync16(uint32_t dst, const void* src) {
    asm volatile("cp.async.cg.shared.global [%0], [%1], 16;" :: "r"(dst), "l"(src));
}
#define CP_COMMIT() asm volatile("cp.async.commit_group;" ::: "memory")
#define CP_WAIT1()  asm volatile("cp.async.wait_group 1;" ::: "memory")
#define CP_WAIT0()  asm volatile("cp.async.wait_group 0;" ::: "memory")

// pack two floats into fp16x2 (elem0 low half)
__device__ __forceinline__ uint32_t packh2(float a, float b) {
    __half2 h = __floats2half2_rn(a, b);
    return *reinterpret_cast<uint32_t*>(&h);
}
// split two fp32 into fp16 hi + fp16 lo-residual pairs
__device__ __forceinline__ void split2h(float a, float b, uint32_t& hi, uint32_t& lo) {
    __half2 h = __floats2half2_rn(a, b);
    float2 hf = __half22float2(h);
    __half2 l = __floats2half2_rn(a - hf.x, b - hf.y);
    hi = *reinterpret_cast<uint32_t*>(&h);
    lo = *reinterpret_cast<uint32_t*>(&l);
}

// ---------------------------------------------------------------------------
// Kernel 0a: split x -> fp16 hi/lo, token norms, batch max norm, zero O/l accs
// ---------------------------------------------------------------------------
__global__ __launch_bounds__(256)
void prep_kernel(const float* __restrict__ x)
{
    const int b = blockIdx.y;
    const int n = blockIdx.x * 256 + threadIdx.x;
    if (n >= NN) return;
    const float* xb = x + (size_t)b * CC * NN;
    __half* hb = g_xhi + (size_t)b * CC * NN;
    __half* lb = g_xlo + (size_t)b * CC * NN;
    float* ob = g_att + (size_t)b * CC * NN;
    float s = 0.f;
    for (int c = 0; c < CC; c++) {
        float v = xb[c * NN + n];
        __half h = __float2half_rn(v);
        hb[c * NN + n] = h;
        lb[c * NN + n] = __float2half_rn(v - __half2float(h));
        ob[c * NN + n] = 0.f;
        s = fmaf(v, v, s);
    }
    float norm = sqrtf(s);
    g_norm[b * NN + n] = norm;
    g_l[b * NN + n] = 0.f;
    atomicMax(&g_maxn[b], __float_as_int(norm));
}

// ---------------------------------------------------------------------------
// Kernel 0b: split + transpose W, zero BN stat accumulators
// ---------------------------------------------------------------------------
__global__ __launch_bounds__(256)
void wprep_kernel(const float* __restrict__ w)
{
    const int i = blockIdx.x * 256 + threadIdx.x;
    if (i < COUT) { g_sum[i] = 0.f; g_sumsq[i] = 0.f; }
    if (i >= COUT * 2 * CC) return;
    const int o = i / (2 * CC), c = i % (2 * CC);
    float v = w[i];
    __half h = __float2half_rn(v);
    g_whi[c * COUT + o] = h;
    g_wlo[c * COUT + o] = __float2half_rn(v - __half2float(h));
}

// ---------------------------------------------------------------------------
// Kernel 1: warp-MMA fp16-split flash attention, online per-block softmax,
// split-K fp32 atomics in the static-bound reference frame.
// S: 3 products; PV: 1 product (Ph*Vh).
// Grid (49, 8, 3) x 128 threads; target 3 blocks/SM (regs capped at 166).
// ---------------------------------------------------------------------------
__global__ __launch_bounds__(128, 3)
void attn_kernel()
{
    extern __shared__ char smc[];
    const uint32_t sb = smem_u32(smc);
    const int tid = threadIdx.x;
    const int lane = tid & 31, warp = tid >> 5;
    const int b  = blockIdx.y;
    const int n0 = blockIdx.x * QTM;
    const int tb = blockIdx.z * 16;
    const int te = (blockIdx.z == KSPLIT - 1) ? NTILE : tb + 16;
    const __half* xh = g_xhi + (size_t)b * CC * NN;
    const __half* xl = g_xlo + (size_t)b * CC * NN;

    // issue Q tile + first K tile (one cp.async group)
    for (int i = tid; i < CC * 8; i += 128) {
        int c = i >> 3, ck = i & 7;
        uint32_t d = swk((uint32_t)(c * 128 + ck * 16));
        cpasync16(sb + OFF_QHI + d, xh + c * NN + n0 + ck * 8);
        cpasync16(sb + OFF_QLO + d, xl + c * NN + n0 + ck * 8);
    }
    {
        const int k0 = tb * TK;
        for (int i = tid; i < CC * 8; i += 128) {
            int c = i >> 3, ck = i & 7;
            uint32_t d = swk((uint32_t)(c * 128 + ck * 16));
            cpasync16(sb + OFF_K + d,         xh + c * NN + k0 + ck * 8);
            cpasync16(sb + OFF_K + 12288 + d, xl + c * NN + k0 + ck * 8);
        }
    }
    CP_COMMIT();

    const float mnorm = __int_as_float(g_maxn[b]);
    const int q0g = warp * 16 + (lane >> 2);
    const int q1g = q0g + 8;
    const float mi0 = g_norm[b * NN + n0 + q0g] * mnorm;  // static upper bound
    const float mi1 = g_norm[b * NN + n0 + q1g] * mnorm;

    float oacc[12][4];
#pragma unroll
    for (int f = 0; f < 12; f++)
#pragma unroll
        for (int e = 0; e < 4; e++) oacc[f][e] = 0.f;
    float l0 = 0.f, l1 = 0.f;
    float m0 = -1e30f, m1 = -1e30f;   // running per-block row max

    uint32_t qah[6][4], qal[6][4];
    const int g  = lane >> 3;
    const int lr = lane & 7;

#pragma unroll 1
    for (int t = tb; t < te; t++) {
        __syncthreads();
        if (t + 1 < te) {
            const int k0 = (t + 1) * TK;
            const uint32_t bs = sb + OFF_K + (uint32_t)((t + 1 - tb) & 1) * KSTAGE;
            for (int i = tid; i < CC * 8; i += 128) {
                int c = i >> 3, ck = i & 7;
                uint32_t d = swk((uint32_t)(c * 128 + ck * 16));
                cpasync16(bs + d,         xh + c * NN + k0 + ck * 8);
                cpasync16(bs + 12288 + d, xl + c * NN + k0 + ck * 8);
            }
            CP_COMMIT();
            CP_WAIT1();
        } else {
            CP_WAIT0();
        }
        __syncthreads();

        if (t == tb) {  // Q fragments (stable afterwards)
#pragma unroll
            for (int k = 0; k < 6; k++) {
                int ch = 16 * k + ((g >= 2) ? 8 : 0) + lr;
                int q  = warp * 16 + ((g & 1) ? 8 : 0);
                uint32_t d = swk((uint32_t)(ch * 128 + q * 2));
                ldsm4t(qah[k], sb + OFF_QHI + d);
                ldsm4t(qal[k], sb + OFF_QLO + d);
            }
        }

        const uint32_t kb = sb + OFF_K + (uint32_t)((t - tb) & 1) * KSTAGE;

        // ---- S = Q K^T (3 split products) ----
        float sacc[8][4];
#pragma unroll
        for (int f = 0; f < 8; f++)
#pragma unroll
            for (int e = 0; e < 4; e++) sacc[f][e] = 0.f;

#pragma unroll
        for (int k = 0; k < 6; k++) {
#pragma unroll
            for (int jp = 0; jp < 4; jp++) {
                int ch  = 16 * k + (g & 1) * 8 + lr;
                int key = 16 * jp + (g >> 1) * 8;
                uint32_t d = swk((uint32_t)(ch * 128 + key * 2));
                uint32_t bh[4], bl[4];
                ldsm4t(bh, kb + d);
                ldsm4t(bl, kb + 12288 + d);
                mma16816(sacc[2 * jp],     qah[k], bh[0], bh[1]);
                mma16816(sacc[2 * jp],     qah[k], bl[0], bl[1]);
                mma16816(sacc[2 * jp],     qal[k], bh[0], bh[1]);
                mma16816(sacc[2 * jp + 1], qah[k], bh[2], bh[3]);
                mma16816(sacc[2 * jp + 1], qah[k], bl[2], bl[3]);
                mma16816(sacc[2 * jp + 1], qal[k], bh[2], bh[3]);
            }
        }

        // ---- online row max; rescale only when the max actually rises ----
        float mx0 = -1e30f, mx1 = -1e30f;
#pragma unroll
        for (int f = 0; f < 8; f++) {
            mx0 = fmaxf(mx0, fmaxf(sacc[f][0], sacc[f][1]));
            mx1 = fmaxf(mx1, fmaxf(sacc[f][2], sacc[f][3]));
        }
        mx0 = fmaxf(mx0, __shfl_xor_sync(0xffffffffu, mx0, 1));
        mx0 = fmaxf(mx0, __shfl_xor_sync(0xffffffffu, mx0, 2));
        mx1 = fmaxf(mx1, __shfl_xor_sync(0xffffffffu, mx1, 1));
        mx1 = fmaxf(mx1, __shfl_xor_sync(0xffffffffu, mx1, 2));
        if (mx0 > m0) {
            float sc0 = __expf(m0 - mx0);   // first tile: exp(-huge) = 0
            m0 = mx0; l0 *= sc0;
#pragma unroll
            for (int f = 0; f < 12; f++) { oacc[f][0] *= sc0; oacc[f][1] *= sc0; }
        }
        if (mx1 > m1) {
            float sc1 = __expf(m1 - mx1);
            m1 = mx1; l1 *= sc1;
#pragma unroll
            for (int f = 0; f < 12; f++) { oacc[f][2] *= sc1; oacc[f][3] *= sc1; }
        }

        // ---- softmax (thread-local, p near 1) -> single fp16 P A-frags ----
        uint32_t pah[4][4];
#pragma unroll
        for (int jj = 0; jj < 4; jj++) {
            float p0 = __expf(sacc[2 * jj][0] - m0);
            float p1 = __expf(sacc[2 * jj][1] - m0);
            float p2 = __expf(sacc[2 * jj][2] - m1);
            float p3 = __expf(sacc[2 * jj][3] - m1);
            float p4 = __expf(sacc[2 * jj + 1][0] - m0);
            float p5 = __expf(sacc[2 * jj + 1][1] - m0);
            float p6 = __expf(sacc[2 * jj + 1][2] - m1);
            float p7 = __expf(sacc[2 * jj + 1][3] - m1);
            l0 += (p0 + p1) + (p4 + p5);
            l1 += (p2 + p3) + (p6 + p7);
            pah[jj][0] = packh2(p0, p1);
            pah[jj][1] = packh2(p2, p3);
            pah[jj][2] = packh2(p4, p5);
            pah[jj][3] = packh2(p6, p7);
        }

        // ---- O += P V (single product: Ph*Vh) ----
#pragma unroll
        for (int jj = 0; jj < 4; jj++) {
#pragma unroll
            for (int cp = 0; cp < 6; cp++) {
                int ch  = 8 * (2 * cp + (g >> 1)) + lr;
                int key = 16 * jj + (g & 1) * 8;
                uint32_t d = swk((uint32_t)(ch * 128 + key * 2));
                uint32_t bh[4];
                ldsm4(bh, kb + d);
                mma16816(oacc[2 * cp],     pah[jj], bh[0], bh[1]);
                mma16816(oacc[2 * cp + 1], pah[jj], bh[2], bh[3]);
            }
        }
    }

    // ---- epilogue: rescale to global (static-bound) frame in fp32, atomics --
    const float f0 = __expf(m0 - mi0);   // <= 1, fp32 range
    const float f1 = __expf(m1 - mi1);

    l0 += __shfl_xor_sync(0xffffffffu, l0, 1);
    l0 += __shfl_xor_sync(0xffffffffu, l0, 2);
    l1 += __shfl_xor_sync(0xffffffffu, l1, 1);
    l1 += __shfl_xor_sync(0xffffffffu, l1, 2);

    float* ob = g_att + (size_t)b * CC * NN + n0;
#pragma unroll
    for (int nf = 0; nf < 12; nf++) {
        int c = 8 * nf + 2 * (lane & 3);
        atomicAdd(&ob[c * NN + q0g],       oacc[nf][0] * f0);
        atomicAdd(&ob[(c + 1) * NN + q0g], oacc[nf][1] * f0);
        atomicAdd(&ob[c * NN + q1g],       oacc[nf][2] * f1);
        atomicAdd(&ob[(c + 1) * NN + q1g], oacc[nf][3] * f1);
    }
    if ((lane & 3) == 0) {
        atomicAdd(&g_l[b * NN + n0 + q0g], l0 * f0);
        atomicAdd(&g_l[b * NN + n0 + q1g], l1 * f1);
    }
}

// ---------------------------------------------------------------------------
// Kernel 2: finalize attention: xj = relu(x - O/l) -> fp16 hi/lo
// ---------------------------------------------------------------------------
__global__ __launch_bounds__(256)
void attn_fin_kernel(const float* __restrict__ x)
{
    const int i4 = blockIdx.x * 256 + threadIdx.x;
    const int per = CC * NN / 4;
    if (i4 >= BB * per) return;
    const int b = i4 / per, r = i4 - b * per;
    const int n4 = r % (NN / 4);
    float4 o  = ((const float4*)g_att)[i4];
    float4 lv = ((const float4*)g_l)[b * (NN / 4) + n4];
    float4 xv = ((const float4*)x)[i4];
    float j0 = fmaxf(xv.x - o.x / lv.x, 0.f);
    float j1 = fmaxf(xv.y - o.y / lv.y, 0.f);
    float j2 = fmaxf(xv.z - o.z / lv.z, 0.f);
    float j3 = fmaxf(xv.w - o.w / lv.w, 0.f);
    uint2 hi, lo;
    split2h(j0, j1, hi.x, lo.x);
    split2h(j2, j3, hi.y, lo.y);
    ((uint2*)g_xjhi)[i4] = hi;
    ((uint2*)g_xjlo)[i4] = lo;
}

// ---------------------------------------------------------------------------
// Kernel 3: 1x1 conv via fp16-split MMA (3 products) + bias + fused BN stats
// Grid (49, 8, 2) x 128 threads; each block: 96 out channels x 64 tokens.
// Warps: wy=warp>>1 -> 48 out rows, wx=warp&1 -> 32 tokens.
// ---------------------------------------------------------------------------
__global__ __launch_bounds__(128)
void conv_kernel(const float* __restrict__ bias)
{
    extern __shared__ char smc[];
    const uint32_t sb = smem_u32(smc);
    const int tid = threadIdx.x;
    const int lane = tid & 31, warp = tid >> 5;
    const int wy = warp >> 1, wx = warp & 1;
    const int b = blockIdx.y, n0 = blockIdx.x * 64;
    const int zo = blockIdx.z * 96;
    const __half* xh = g_xhi  + (size_t)b * CC * NN;
    const __half* xl = g_xlo  + (size_t)b * CC * NN;
    const __half* jh = g_xjhi + (size_t)b * CC * NN;
    const __half* jl = g_xjlo + (size_t)b * CC * NN;

    // cat tile [192 ch][64 tok] + W chunk 0 (one group)
    for (int i = tid; i < 192 * 8; i += 128) {
        int c = i >> 3, ck = i & 7;
        uint32_t d = swk((uint32_t)(c * 128 + ck * 16));
        const __half* sh = (c < CC) ? (xh + c * NN) : (jh + (c - CC) * NN);
        const __half* sl = (c < CC) ? (xl + c * NN) : (jl + (c - CC) * NN);
        cpasync16(sb + CV_CAT_HI + d, sh + n0 + ck * 8);
        cpasync16(sb + CV_CAT_LO + d, sl + n0 + ck * 8);
    }
    for (int i = tid; i < 16 * 12; i += 128) {
        int rr = i / 12, cc = i % 12;
        cpasync16(sb + CV_W + rr * 208 + cc * 16,            g_whi + rr * COUT + zo + cc * 8);
        cpasync16(sb + CV_W + CV_WHALF + rr * 208 + cc * 16, g_wlo + rr * COUT + zo + cc * 8);
    }
    CP_COMMIT();

    float cacc[3][4][4];
#pragma unroll
    for (int m = 0; m < 3; m++)
#pragma unroll
        for (int n = 0; n < 4; n++)
#pragma unroll
            for (int e = 0; e < 4; e++) cacc[m][n][e] = 0.f;

    const int g = lane >> 3, lr = lane & 7;

#pragma unroll 1
    for (int k = 0; k < 12; k++) {
        if (k + 1 < 12) {
            const uint32_t wb = sb + CV_W + (uint32_t)((k + 1) & 1) * CV_WSTAGE;
            const int k0n = (k + 1) * 16;
            for (int i = tid; i < 16 * 12; i += 128) {
                int rr = i / 12, cc = i % 12;
                cpasync16(wb + rr * 208 + cc * 16,            g_whi + (k0n + rr) * COUT + zo + cc * 8);
                cpasync16(wb + CV_WHALF + rr * 208 + cc * 16, g_wlo + (k0n + rr) * COUT + zo + cc * 8);
            }
            CP_COMMIT();
            CP_WAIT1();
        } else {
            CP_WAIT0();
        }
        __syncthreads();

        const uint32_t wb = sb + CV_W + (uint32_t)(k & 1) * CV_WSTAGE;
        uint32_t ah[3][4], al[3][4];
#pragma unroll
        for (int mf = 0; mf < 3; mf++) {
            int out = 48 * wy + 16 * mf + ((g & 1) ? 8 : 0);
            int chh = ((g >= 2) ? 8 : 0) + lr;
            uint32_t d = (uint32_t)(chh * 208 + out * 2);
            ldsm4t(ah[mf], wb + d);
            ldsm4t(al[mf], wb + CV_WHALF + d);
        }
#pragma unroll
        for (int jp = 0; jp < 2; jp++) {
            int ch  = k * 16 + (g & 1) * 8 + lr;
            int key = 32 * wx + 16 * jp + (g >> 1) * 8;
            uint32_t d = swk((uint32_t)(ch * 128 + key * 2));
            uint32_t bh[4], bl[4];
            ldsm4t(bh, sb + CV_CAT_HI + d);
            ldsm4t(bl, sb + CV_CAT_LO + d);
#pragma unroll
            for (int mf = 0; mf < 3; mf++) {
                mma16816(cacc[mf][2 * jp],     ah[mf], bh[0], bh[1]);
                mma16816(cacc[mf][2 * jp],     ah[mf], bl[0], bl[1]);
                mma16816(cacc[mf][2 * jp],     al[mf], bh[0], bh[1]);
                mma16816(cacc[mf][2 * jp + 1], ah[mf], bh[2], bh[3]);
                mma16816(cacc[mf][2 * jp + 1], ah[mf], bl[2], bl[3]);
                mma16816(cacc[mf][2 * jp + 1], al[mf], bh[2], bh[3]);
            }
        }
        __syncthreads();
    }

    // ---- bias, stage y in smem (96 rows, stride 65 floats) ----
    float* ys = (float*)smc;
#pragma unroll
    for (int mf = 0; mf < 3; mf++) {
        int r0 = 48 * wy + 16 * mf + (lane >> 2);
        float b0 = bias[zo + r0], b1 = bias[zo + r0 + 8];
#pragma unroll
        for (int nf = 0; nf < 4; nf++) {
            int tok = 32 * wx + 8 * nf + 2 * (lane & 3);
            ys[r0 * 65 + tok]           = cacc[mf][nf][0] + b0;
            ys[r0 * 65 + tok + 1]       = cacc[mf][nf][1] + b0;
            ys[(r0 + 8) * 65 + tok]     = cacc[mf][nf][2] + b1;
            ys[(r0 + 8) * 65 + tok + 1] = cacc[mf][nf][3] + b1;
        }
    }
    __syncthreads();

    // ---- partial BN stats (96 channels/block) ----
    if (tid < 96) {
        float s = 0.f, ss = 0.f;
#pragma unroll 4
        for (int i = 0; i < 64; i++) {
            float v = ys[tid * 65 + i];
            s += v; ss = fmaf(v, v, ss);
        }
        atomicAdd(&g_sum[zo + tid], s);
        atomicAdd(&g_sumsq[zo + tid], ss);
    }

    // ---- write y (coalesced) ----
    float* yb = g_y + (size_t)b * COUT * NN + (size_t)zo * NN + n0;
    for (int i = tid; i < 96 * 64; i += 128) {
        int rr = i >> 6, cc = i & 63;
        yb[rr * NN + cc] = ys[rr * 65 + cc];
    }
}

// ---------------------------------------------------------------------------
// Kernel 4: BN apply (scale/shift computed inline from stats) + exact GELU
// ---------------------------------------------------------------------------
__global__ __launch_bounds__(256)
void bn_gelu_kernel(float* __restrict__ out,
                    const float* __restrict__ gamma,
                    const float* __restrict__ beta)
{
    const int i4 = blockIdx.x * blockDim.x + threadIdx.x;
    const int total4 = BB * COUT * NN / 4;
    if (i4 >= total4) return;
    const int ch = (i4 / (NN / 4)) % COUT;
    const float cnt = (float)(BB * NN);
    const float mean = g_sum[ch] / cnt;
    const float var  = g_sumsq[ch] / cnt - mean * mean;
    const float a    = gamma[ch] * rsqrtf(var + 1e-5f);
    const float sh   = beta[ch] - mean * a;
    float4 v = ((const float4*)g_y)[i4];
    v.x = v.x * a + sh;  v.x = v.x * normcdff(v.x);
    v.y = v.y * a + sh;  v.y = v.y * normcdff(v.y);
    v.z = v.z * a + sh;  v.z = v.z * normcdff(v.z);
    v.w = v.w * a + sh;  v.w = v.w * normcdff(v.w);
    ((float4*)out)[i4] = v;
}

// ---------------------------------------------------------------------------
extern "C" void kernel_launch(void* const* d_in, const int* in_sizes, int n_in,
                              void* d_out, int out_size)
{
    const float* x     = (const float*)d_in[0];
    const float* w     = (const float*)d_in[1];
    const float* cbias = (const float*)d_in[2];
    const float* gamma = (const float*)d_in[3];
    const float* beta  = (const float*)d_in[4];
    float* out = (float*)d_out;

    cudaFuncSetAttribute(attn_kernel, cudaFuncAttributeMaxDynamicSharedMemorySize, ATT_SMEM);
    cudaFuncSetAttribute(conv_kernel, cudaFuncAttributeMaxDynamicSharedMemorySize, CV_SMEM);

    prep_kernel<<<dim3((NN + 255) / 256, BB), 256>>>(x);
    wprep_kernel<<<(COUT * 2 * CC + 255) / 256, 256>>>(w);
    attn_kernel<<<dim3(NTILE, BB, KSPLIT), 128, ATT_SMEM>>>();
    attn_fin_kernel<<<(BB * CC * NN / 4 + 255) / 256, 256>>>(x);
    conv_kernel<<<dim3(NTILE, BB, 2), 128, CV_SMEM>>>(cbias);
    bn_gelu_kernel<<<(BB * COUT * NN / 4 + 255) / 256, 256>>>(out, gamma, beta);
}